// round 4
// baseline (speedup 1.0000x reference)
#include <cuda_runtime.h>
#include <math.h>

#define BB  4
#define SS  256
#define VV  64
#define HH  128
#define NHH 8
#define DHH 16
#define NLL 3
#define LLP1 11
#define MM  (BB*SS)   // 1024

// -------- device scratch (static; allocation-free) --------
__device__ float g_adj[VV*VV*LLP1];
__device__ float g_Z1[(size_t)VV*MM*HH];
__device__ float g_Z2[(size_t)VV*MM*HH];
__device__ float g_Qb[(size_t)VV*MM*HH];
__device__ float g_Kb[(size_t)VV*MM*HH];
__device__ float g_Vb[(size_t)VV*MM*HH];

__device__ __forceinline__ float* buf_sel(int s) {
    return (s == 0) ? g_Z1 : (s == 1) ? g_Z2 : (s == 2) ? g_Qb : (s == 3) ? g_Kb : g_Vb;
}

// -------- kernel 0: sigmoid of adjacency logits --------
__global__ void sigmoid_adj_kernel(const float* __restrict__ logits) {
    int idx = blockIdx.x * blockDim.x + threadIdx.x;
    if (idx < VV*VV*LLP1) {
        float v = logits[idx];
        g_adj[idx] = 1.f / (1.f + expf(-v));
    }
}

// -------- kernel 1: causal input z[i][m][h] into g_Z1 --------
// z[i,m,h] = sum_s A[s]*var_emb[s,h] + sum_l Bl[l]*temp_emb[l,h]
// A[s]  = sum_l x[b,t-l,s]*adj[s,i,l]
// Bl[l] = sum_s x[b,t-l,s]*adj[s,i,l]
__global__ void causal_kernel(const float* __restrict__ x,
                              const float* __restrict__ var_emb,
                              const float* __restrict__ temp_emb) {
    const int m = blockIdx.x;          // 0..1023
    const int i = blockIdx.y;          // target variable
    const int b = m >> 8;
    const int t = m & 255;

    __shared__ float prods[64][12];
    __shared__ float Ash[64];
    __shared__ float Blsh[LLP1];

    const int tid = threadIdx.x;       // 128 threads
    if (tid < 64) {
        const int s = tid;
        const float* adjp = g_adj + ((size_t)s*VV + i)*LLP1;
        float a = 0.f;
        #pragma unroll
        for (int l = 0; l < LLP1; l++) {
            float xv = (t - l >= 0) ? x[((size_t)b*SS + (t - l))*VV + s] : 0.f;
            float p = xv * adjp[l];
            prods[s][l] = p;
            a += p;
        }
        Ash[s] = a;
    }
    __syncthreads();
    if (tid >= 64 && tid < 64 + LLP1) {
        const int l = tid - 64;
        float bl = 0.f;
        #pragma unroll 8
        for (int s = 0; s < 64; s++) bl += prods[s][l];
        Blsh[l] = bl;
    }
    __syncthreads();

    const int h = tid;                 // 0..127
    float acc = 0.f;
    #pragma unroll 8
    for (int s = 0; s < 64; s++) acc += Ash[s] * var_emb[s*HH + h];
    #pragma unroll
    for (int l = 0; l < LLP1; l++) acc += Blsh[l] * temp_emb[l*HH + h];
    g_Z1[((size_t)i*MM + m)*HH + h] = acc;
}

// -------- kernel 2: batched per-variable GEMM, fused epilogue --------
// Y[v][m][k] = X[v][m][:] @ W[v][:][k] + bias[v][k]
// MODE 0: + LayerNorm + exact GELU (mech layer li)
// MODE 1: bias only (Q/K/V/O projections)
template <int MODE>
__global__ void __launch_bounds__(256, 4)
gemm_kernel(int src, int dst,
            const float* __restrict__ Wall, const float* __restrict__ ball,
            const float* __restrict__ lng, const float* __restrict__ lnb,
            int li) {
    const int v  = blockIdx.y;
    const int m0 = blockIdx.x * 64;

    const float* X = buf_sel(src);
    float*       Y = buf_sel(dst);

    const float* Wv = (MODE == 0) ? Wall + ((size_t)v*NLL + li)*HH*HH
                                  : Wall + (size_t)v*HH*HH;
    const float* bv = (MODE == 0) ? ball + ((size_t)v*NLL + li)*HH
                                  : ball + (size_t)v*HH;
    const float* Xv = X + ((size_t)v*MM + m0)*HH;

    __shared__ float As[16][65];
    __shared__ float Bs[16][128];

    float acc[8][4];
    #pragma unroll
    for (int r = 0; r < 8; r++)
        #pragma unroll
        for (int c = 0; c < 4; c++) acc[r][c] = 0.f;

    const int tid  = threadIdx.x;
    const int w    = tid >> 5;     // warp 0..7 -> rows w*8..w*8+7
    const int lane = tid & 31;     // cols lane*4..lane*4+3
    const int arow = tid >> 2;     // A loader: row 0..63
    const int aseg = tid & 3;      // A loader: 4-float segment
    const int brow = tid >> 4;     // B loader: k 0..15
    const int bseg = tid & 15;     // B loader: 8-float col segment

    for (int k0 = 0; k0 < HH; k0 += 16) {
        float4 av = *(const float4*)(Xv + (size_t)arow*HH + k0 + aseg*4);
        As[aseg*4 + 0][arow] = av.x;
        As[aseg*4 + 1][arow] = av.y;
        As[aseg*4 + 2][arow] = av.z;
        As[aseg*4 + 3][arow] = av.w;

        const float* wp = Wv + (size_t)(k0 + brow)*HH + bseg*8;
        float4 w0 = *(const float4*)(wp);
        float4 w1 = *(const float4*)(wp + 4);
        *(float4*)&Bs[brow][bseg*8 + 0] = w0;
        *(float4*)&Bs[brow][bseg*8 + 4] = w1;
        __syncthreads();

        #pragma unroll
        for (int kk = 0; kk < 16; kk++) {
            float a[8];
            #pragma unroll
            for (int r = 0; r < 8; r++) a[r] = As[kk][w*8 + r];
            float4 bb = *(const float4*)&Bs[kk][lane*4];
            #pragma unroll
            for (int r = 0; r < 8; r++) {
                acc[r][0] += a[r]*bb.x;
                acc[r][1] += a[r]*bb.y;
                acc[r][2] += a[r]*bb.z;
                acc[r][3] += a[r]*bb.w;
            }
        }
        __syncthreads();
    }

    // bias
    float4 bias = *(const float4*)(bv + lane*4);
    #pragma unroll
    for (int r = 0; r < 8; r++) {
        acc[r][0] += bias.x; acc[r][1] += bias.y;
        acc[r][2] += bias.z; acc[r][3] += bias.w;
    }

    if (MODE == 0) {
        // LayerNorm over H=128 (one warp owns full rows) + exact GELU
        const float* gp = lng + ((size_t)v*NLL + li)*HH;
        const float* bp = lnb + ((size_t)v*NLL + li)*HH;
        float4 gv4 = *(const float4*)(gp + lane*4);
        float4 bv4 = *(const float4*)(bp + lane*4);
        float gg[4] = {gv4.x, gv4.y, gv4.z, gv4.w};
        float bt[4] = {bv4.x, bv4.y, bv4.z, bv4.w};
        #pragma unroll
        for (int r = 0; r < 8; r++) {
            float s1 = acc[r][0] + acc[r][1] + acc[r][2] + acc[r][3];
            float s2 = acc[r][0]*acc[r][0] + acc[r][1]*acc[r][1]
                     + acc[r][2]*acc[r][2] + acc[r][3]*acc[r][3];
            #pragma unroll
            for (int o = 16; o > 0; o >>= 1) {
                s1 += __shfl_xor_sync(0xffffffffu, s1, o);
                s2 += __shfl_xor_sync(0xffffffffu, s2, o);
            }
            float mu  = s1 * (1.f/128.f);
            float var = s2 * (1.f/128.f) - mu*mu;
            float inv = rsqrtf(var + 1e-5f);
            #pragma unroll
            for (int c = 0; c < 4; c++) {
                float xx = (acc[r][c] - mu) * inv * gg[c] + bt[c];
                acc[r][c] = 0.5f * xx * (1.f + erff(xx * 0.70710678118654752f));
            }
        }
    }

    float* Yv = Y + ((size_t)v*MM + m0)*HH;
    #pragma unroll
    for (int r = 0; r < 8; r++) {
        float4 st = make_float4(acc[r][0], acc[r][1], acc[r][2], acc[r][3]);
        *(float4*)(Yv + (size_t)(w*8 + r)*HH + lane*4) = st;
    }
}

// -------- kernel 3: per-(b,v,head) attention, online softmax --------
// one query row per thread; K/V tiles in smem (broadcast reads)
__global__ void __launch_bounds__(256, 4) attn_kernel() {
    const int n = blockIdx.x;   // head
    const int v = blockIdx.y;
    const int b = blockIdx.z;

    __shared__ float Ks[SS][DHH];
    __shared__ float Vs[SS][DHH];

    const int tid = threadIdx.x;   // query index t
    const size_t base = ((size_t)v*MM + (size_t)b*SS)*HH + n*DHH;
    const float* Qp = g_Qb + base + (size_t)tid*HH;
    const float* Kp = g_Kb + base + (size_t)tid*HH;
    const float* Vp = g_Vb + base + (size_t)tid*HH;

    float q[16];
    #pragma unroll
    for (int j = 0; j < 4; j++) {
        float4 qv = *(const float4*)(Qp + j*4);
        q[j*4+0] = qv.x; q[j*4+1] = qv.y; q[j*4+2] = qv.z; q[j*4+3] = qv.w;
        *(float4*)&Ks[tid][j*4] = *(const float4*)(Kp + j*4);
        *(float4*)&Vs[tid][j*4] = *(const float4*)(Vp + j*4);
    }
    __syncthreads();

    float mx = -3.0e38f, lsum = 0.f;
    float acc[16];
    #pragma unroll
    for (int d = 0; d < 16; d++) acc[d] = 0.f;

    for (int j = 0; j < SS; j++) {
        float s = 0.f;
        #pragma unroll
        for (int d = 0; d < 16; d++) s += q[d] * Ks[j][d];
        s *= 0.25f;  // 1/sqrt(DH)
        if (s > mx) {
            float f = __expf(mx - s);
            lsum *= f;
            #pragma unroll
            for (int d = 0; d < 16; d++) acc[d] *= f;
            mx = s;
        }
        float p = __expf(s - mx);
        lsum += p;
        #pragma unroll
        for (int d = 0; d < 16; d++) acc[d] += p * Vs[j][d];
    }

    float inv = 1.f / lsum;
    float* Op = g_Z1 + base + (size_t)tid*HH;
    #pragma unroll
    for (int j = 0; j < 4; j++) {
        float4 st = make_float4(acc[j*4+0]*inv, acc[j*4+1]*inv,
                                acc[j*4+2]*inv, acc[j*4+3]*inv);
        *(float4*)(Op + j*4) = st;
    }
}

// -------- kernel 4: output head --------
__global__ void head_kernel(const float* __restrict__ out_W,
                            const float* __restrict__ out_b,
                            float* __restrict__ out) {
    const int gw   = (blockIdx.x * 256 + threadIdx.x) >> 5;
    const int lane = threadIdx.x & 31;
    if (gw >= VV*MM) return;
    const int v = gw >> 10;
    const int m = gw & 1023;
    const float* xp = g_Z2 + (size_t)gw*HH;
    const float* wp = out_W + (size_t)v*HH;
    float4 xv = *(const float4*)(xp + lane*4);
    float4 wv = *(const float4*)(wp + lane*4);
    float s = xv.x*wv.x + xv.y*wv.y + xv.z*wv.z + xv.w*wv.w;
    #pragma unroll
    for (int o = 16; o > 0; o >>= 1) s += __shfl_xor_sync(0xffffffffu, s, o);
    if (lane == 0) out[(size_t)m*VV + v] = s + out_b[v];
}

extern "C" void kernel_launch(void* const* d_in, const int* in_sizes, int n_in,
                              void* d_out, int out_size) {
    const float* x        = (const float*)d_in[0];
    const float* adjl     = (const float*)d_in[1];
    const float* var_emb  = (const float*)d_in[2];
    const float* temp_emb = (const float*)d_in[3];
    const float* mech_W   = (const float*)d_in[4];
    const float* mech_b   = (const float*)d_in[5];
    const float* ln_g     = (const float*)d_in[6];
    const float* ln_b     = (const float*)d_in[7];
    const float* Wq       = (const float*)d_in[8];
    const float* Wk       = (const float*)d_in[9];
    const float* Wv       = (const float*)d_in[10];
    const float* Wo       = (const float*)d_in[11];
    const float* bq       = (const float*)d_in[12];
    const float* bk       = (const float*)d_in[13];
    const float* bv       = (const float*)d_in[14];
    const float* bo       = (const float*)d_in[15];
    const float* out_W    = (const float*)d_in[16];
    const float* out_b    = (const float*)d_in[17];
    float* out = (float*)d_out;

    sigmoid_adj_kernel<<<(VV*VV*LLP1 + 255)/256, 256>>>(adjl);
    causal_kernel<<<dim3(MM, VV), 128>>>(x, var_emb, temp_emb);

    // mech layers: Z1 -> Z2 -> Z1 -> Z2
    gemm_kernel<0><<<dim3(16, VV), 256>>>(0, 1, mech_W, mech_b, ln_g, ln_b, 0);
    gemm_kernel<0><<<dim3(16, VV), 256>>>(1, 0, mech_W, mech_b, ln_g, ln_b, 1);
    gemm_kernel<0><<<dim3(16, VV), 256>>>(0, 1, mech_W, mech_b, ln_g, ln_b, 2);

    // projections from Z2
    gemm_kernel<1><<<dim3(16, VV), 256>>>(1, 2, Wq, bq, nullptr, nullptr, 0);
    gemm_kernel<1><<<dim3(16, VV), 256>>>(1, 3, Wk, bk, nullptr, nullptr, 0);
    gemm_kernel<1><<<dim3(16, VV), 256>>>(1, 4, Wv, bv, nullptr, nullptr, 0);

    // attention -> Z1
    attn_kernel<<<dim3(NHH, VV, BB), 256>>>();

    // output projection Z1 -> Z2
    gemm_kernel<1><<<dim3(16, VV), 256>>>(0, 1, Wo, bo, nullptr, nullptr, 0);

    // head
    head_kernel<<<(VV*MM/8 + 0), 256>>>(out_W, out_b, out);
}

// round 6
// speedup vs baseline: 1.4524x; 1.4524x over previous
#include <cuda_runtime.h>
#include <math.h>
#include <stdint.h>

#define BB  4
#define SS  256
#define VV  64
#define HH  128
#define NHH 8
#define DHH 16
#define NLL 3
#define LLP1 11
#define MM  (BB*SS)   // 1024
#define KAB 96        // padded causal K (64 A + 11 Bl + 21 zero)

// -------- device scratch (static; allocation-free) --------
__device__ float g_adj[VV*VV*LLP1];
__device__ float g_Z1[(size_t)VV*MM*HH];
__device__ float g_Z2[(size_t)VV*MM*HH];
__device__ float g_Qb[(size_t)VV*MM*HH];
__device__ float g_Kb[(size_t)VV*MM*HH];
__device__ float g_Vb[(size_t)VV*MM*HH];
__device__ float g_AB[(size_t)VV*KAB*MM];   // k-major: [v][k][m]
__device__ float g_Wc[KAB*HH];
__device__ float g_weff[VV*HH];
__device__ float g_beff[VV];

__device__ __forceinline__ float* buf_sel(int s) {
    return (s == 0) ? g_Z1 : (s == 1) ? g_Z2 : (s == 2) ? g_Qb
         : (s == 3) ? g_Kb : (s == 4) ? g_Vb : g_AB;
}

__device__ __forceinline__ void cpasync16(uint32_t saddr, const void* g) {
    asm volatile("cp.async.cg.shared.global [%0], [%1], 16;\n" :: "r"(saddr), "l"(g));
}

// -------- sigmoid of adjacency logits --------
__global__ void sigmoid_adj_kernel(const float* __restrict__ logits) {
    int idx = blockIdx.x * blockDim.x + threadIdx.x;
    if (idx < VV*VV*LLP1) {
        float v = logits[idx];
        g_adj[idx] = 1.f / (1.f + expf(-v));
    }
}

// -------- build shared causal weight Wc[96][128] = [var_emb; temp_emb; 0] --------
__global__ void build_Wc_kernel(const float* __restrict__ var_emb,
                                const float* __restrict__ temp_emb) {
    int idx = blockIdx.x * 256 + threadIdx.x;
    if (idx >= KAB*HH) return;
    int r = idx >> 7, h = idx & 127;
    float val = 0.f;
    if (r < VV) val = var_emb[r*HH + h];
    else if (r < VV + LLP1) val = temp_emb[(r - VV)*HH + h];
    g_Wc[idx] = val;
}

// -------- fold O-proj into output head: weff[v]=Wo[v]@outW[v], beff[v]=bo.outW+outb --------
__global__ void build_weff_kernel(const float* __restrict__ Wo,
                                  const float* __restrict__ bo,
                                  const float* __restrict__ outW,
                                  const float* __restrict__ outb) {
    const int v = blockIdx.x;
    const int h = threadIdx.x;   // 128
    __shared__ float sw[HH];
    __shared__ float red[HH];
    sw[h] = outW[v*HH + h];
    __syncthreads();
    const float* wp = Wo + ((size_t)v*HH + h)*HH;
    float s = 0.f;
    #pragma unroll 8
    for (int k = 0; k < HH; k++) s = fmaf(wp[k], sw[k], s);
    g_weff[v*HH + h] = s;
    red[h] = bo[v*HH + h] * sw[h];
    __syncthreads();
    #pragma unroll
    for (int o = 64; o > 0; o >>= 1) {
        if (h < o) red[h] += red[h + o];
        __syncthreads();
    }
    if (h == 0) g_beff[v] = red[0] + outb[v];
}

// -------- stage AB_T[i][k][m]: A (k<64), Bl (64<=k<75), zeros (75..95) --------
// one block per (target var i, batch b, half hb); 128 timesteps per block
__global__ void __launch_bounds__(128) build_AB_kernel(const float* __restrict__ x) {
    const int i  = blockIdx.x;
    const int b  = blockIdx.y;
    const int t0 = blockIdx.z * 128;
    __shared__ float xsh[VV][140];   // j in 0..137 -> t = t0-10+j (zero-filled for t<0)
    __shared__ float adjs[VV][12];
    const int tid = threadIdx.x;     // 128

    for (int f = tid; f < 138*16; f += 128) {
        int j = f >> 4, s4 = f & 15;
        int t = t0 - 10 + j;
        float4 xv = make_float4(0.f, 0.f, 0.f, 0.f);
        if (t >= 0) xv = *(const float4*)(x + ((size_t)(b*SS + t))*VV + s4*4);
        xsh[s4*4+0][j] = xv.x;
        xsh[s4*4+1][j] = xv.y;
        xsh[s4*4+2][j] = xv.z;
        xsh[s4*4+3][j] = xv.w;
    }
    for (int f = tid; f < VV*LLP1; f += 128) {
        int s = f / LLP1, l = f - s*LLP1;
        adjs[s][l] = g_adj[((size_t)s*VV + i)*LLP1 + l];
    }
    __syncthreads();

    const int j0 = tid + 10;         // tap index of lag 0
    float bl[LLP1];
    #pragma unroll
    for (int l = 0; l < LLP1; l++) bl[l] = 0.f;

    float* ABi = g_AB + (size_t)i*KAB*MM + b*SS + t0;
    #pragma unroll 2
    for (int s = 0; s < VV; s++) {
        const float* xr = xsh[s];
        const float* ar = adjs[s];
        float a = 0.f;
        #pragma unroll
        for (int l = 0; l < LLP1; l++) {
            float p = xr[j0 - l] * ar[l];
            a += p;
            bl[l] += p;
        }
        ABi[(size_t)s*MM + tid] = a;
    }
    #pragma unroll
    for (int l = 0; l < LLP1; l++) ABi[(size_t)(VV + l)*MM + tid] = bl[l];
    #pragma unroll
    for (int r = VV + LLP1; r < KAB; r++) ABi[(size_t)r*MM + tid] = 0.f;
}

// -------- batched per-variable GEMM (64x128 tile, KT=32, double-buffered) --------
// MODE 0: bias + LayerNorm + exact GELU   MODE 1: bias   MODE 2: plain
// XT:  X stored k-major [KDIM][MM] per v (causal AB path)
// SHW: shared weight g_Wc (ignore Wall)
template<int MODE, int KDIM, bool XT, bool SHW>
__global__ void __launch_bounds__(256, 2)
gemm2(int src, int dst,
      const float* __restrict__ Wall, const float* __restrict__ ball,
      const float* __restrict__ lng, const float* __restrict__ lnb, int li)
{
    constexpr int NK = KDIM / 32;
    __shared__ float As[2][32][64];   // 16 KB
    __shared__ float Bs[2][32][128];  // 32 KB  (total 48 KB exactly)
    const uint32_t As_u = (uint32_t)__cvta_generic_to_shared(&As[0][0][0]);
    const uint32_t Bs_u = (uint32_t)__cvta_generic_to_shared(&Bs[0][0][0]);

    const int v   = blockIdx.y;
    const int m0  = blockIdx.x * 64;
    const int tid = threadIdx.x;
    const int w = tid >> 5, lane = tid & 31;

    const float* Xb = buf_sel(src);
    const float* Xv = XT ? (Xb + (size_t)v*KDIM*MM)
                         : (Xb + ((size_t)v*MM + m0)*KDIM);
    const float* Wv = SHW ? g_Wc
                    : (MODE == 0 ? Wall + ((size_t)v*NLL + li)*HH*HH
                                 : Wall + (size_t)v*HH*HH);

    float acc[8][4];
    #pragma unroll
    for (int r = 0; r < 8; r++) { acc[r][0]=0.f; acc[r][1]=0.f; acc[r][2]=0.f; acc[r][3]=0.f; }

    const int am = tid >> 2, ak = tid & 3;      // !XT loader
    const int xkr = tid >> 3, xms = tid & 7;    // XT loader
    float4 pa0, pa1;

    auto issueA = [&](int k0, int buf) {
        if (XT) {
            const float* g = Xv + (size_t)(k0 + xkr)*MM + m0 + xms*8;
            uint32_t d = As_u + (uint32_t)((buf*2048 + xkr*64 + xms*8) * 4);
            cpasync16(d, g);
            cpasync16(d + 16, g + 4);
        } else {
            const float* g = Xv + (size_t)am*KDIM + k0 + ak*8;
            pa0 = *(const float4*)g;
            pa1 = *(const float4*)(g + 4);
        }
    };
    auto storeA = [&](int buf) {
        if (!XT) {
            float* base = &As[buf][0][0] + am;
            base[(ak*8+0)*64] = pa0.x; base[(ak*8+1)*64] = pa0.y;
            base[(ak*8+2)*64] = pa0.z; base[(ak*8+3)*64] = pa0.w;
            base[(ak*8+4)*64] = pa1.x; base[(ak*8+5)*64] = pa1.y;
            base[(ak*8+6)*64] = pa1.z; base[(ak*8+7)*64] = pa1.w;
        }
    };
    auto issueB = [&](int k0, int buf) {
        #pragma unroll
        for (int i2 = 0; i2 < 4; i2++) {
            int s = tid + i2*256;
            int kr = s >> 5, c4 = (s & 31) << 2;
            uint32_t d = Bs_u + (uint32_t)((buf*4096 + kr*128 + c4) * 4);
            cpasync16(d, Wv + (size_t)(k0 + kr)*HH + c4);
        }
    };

    issueA(0, 0);
    issueB(0, 0);
    storeA(0);
    asm volatile("cp.async.commit_group;\n");
    asm volatile("cp.async.wait_group 0;\n" ::: "memory");
    __syncthreads();

    #pragma unroll 1
    for (int kt = 0; kt < NK; kt++) {
        const int cur = kt & 1, nxt = cur ^ 1;
        if (kt + 1 < NK) {
            issueA((kt + 1)*32, nxt);
            issueB((kt + 1)*32, nxt);
            asm volatile("cp.async.commit_group;\n");
        }
        const float* Ap = &As[cur][0][0] + w*8;
        const float* Bp = &Bs[cur][0][0] + (lane << 2);
        #pragma unroll 8
        for (int kk = 0; kk < 32; kk++) {
            float4 a0 = *(const float4*)(Ap + kk*64);
            float4 a1 = *(const float4*)(Ap + kk*64 + 4);
            float4 b  = *(const float4*)(Bp + kk*128);
            float ar[8] = {a0.x,a0.y,a0.z,a0.w,a1.x,a1.y,a1.z,a1.w};
            #pragma unroll
            for (int r = 0; r < 8; r++) {
                acc[r][0] = fmaf(ar[r], b.x, acc[r][0]);
                acc[r][1] = fmaf(ar[r], b.y, acc[r][1]);
                acc[r][2] = fmaf(ar[r], b.z, acc[r][2]);
                acc[r][3] = fmaf(ar[r], b.w, acc[r][3]);
            }
        }
        if (kt + 1 < NK) {
            storeA(nxt);
            asm volatile("cp.async.wait_group 0;\n" ::: "memory");
            __syncthreads();
        }
    }

    if (MODE < 2) {
        const float* bv = (MODE == 0) ? ball + ((size_t)v*NLL + li)*HH
                                      : ball + (size_t)v*HH;
        float4 bias = *(const float4*)(bv + lane*4);
        #pragma unroll
        for (int r = 0; r < 8; r++) {
            acc[r][0] += bias.x; acc[r][1] += bias.y;
            acc[r][2] += bias.z; acc[r][3] += bias.w;
        }
    }

    if (MODE == 0) {
        const float* gp = lng + ((size_t)v*NLL + li)*HH;
        const float* bp = lnb + ((size_t)v*NLL + li)*HH;
        float4 gv4 = *(const float4*)(gp + lane*4);
        float4 bv4 = *(const float4*)(bp + lane*4);
        float gg[4] = {gv4.x, gv4.y, gv4.z, gv4.w};
        float bt[4] = {bv4.x, bv4.y, bv4.z, bv4.w};
        #pragma unroll
        for (int r = 0; r < 8; r++) {
            float s1 = acc[r][0] + acc[r][1] + acc[r][2] + acc[r][3];
            float s2 = acc[r][0]*acc[r][0] + acc[r][1]*acc[r][1]
                     + acc[r][2]*acc[r][2] + acc[r][3]*acc[r][3];
            #pragma unroll
            for (int o = 16; o > 0; o >>= 1) {
                s1 += __shfl_xor_sync(0xffffffffu, s1, o);
                s2 += __shfl_xor_sync(0xffffffffu, s2, o);
            }
            float mu  = s1 * (1.f/128.f);
            float var = s2 * (1.f/128.f) - mu*mu;
            float inv = rsqrtf(var + 1e-5f);
            #pragma unroll
            for (int c = 0; c < 4; c++) {
                float xx = (acc[r][c] - mu) * inv * gg[c] + bt[c];
                acc[r][c] = 0.5f * xx * (1.f + erff(xx * 0.70710678118654752f));
            }
        }
    }

    float* Yv = buf_sel(dst) + ((size_t)v*MM + m0)*HH;
    #pragma unroll
    for (int r = 0; r < 8; r++) {
        float4 st = make_float4(acc[r][0], acc[r][1], acc[r][2], acc[r][3]);
        *(float4*)(Yv + (size_t)(w*8 + r)*HH + lane*4) = st;
    }
}

// -------- attention: per-(b,v,head), one query per thread, online softmax --------
__global__ void __launch_bounds__(256) attn_kernel() {
    const int n = blockIdx.x, v = blockIdx.y, b = blockIdx.z;
    __shared__ __align__(16) float Ks[SS][DHH];
    __shared__ __align__(16) float Vs[SS][DHH];

    const int t = threadIdx.x;
    const size_t base = ((size_t)v*MM + (size_t)b*SS)*HH + n*DHH;
    const float* Qp = g_Qb + base + (size_t)t*HH;
    const float* Kp = g_Kb + base + (size_t)t*HH;
    const float* Vp = g_Vb + base + (size_t)t*HH;

    float4 q0 = *(const float4*)(Qp);
    float4 q1 = *(const float4*)(Qp + 4);
    float4 q2 = *(const float4*)(Qp + 8);
    float4 q3 = *(const float4*)(Qp + 12);
    const float sc = 0.25f;  // 1/sqrt(DH)
    q0.x*=sc; q0.y*=sc; q0.z*=sc; q0.w*=sc;
    q1.x*=sc; q1.y*=sc; q1.z*=sc; q1.w*=sc;
    q2.x*=sc; q2.y*=sc; q2.z*=sc; q2.w*=sc;
    q3.x*=sc; q3.y*=sc; q3.z*=sc; q3.w*=sc;
    #pragma unroll
    for (int j = 0; j < 4; j++) {
        *(float4*)&Ks[t][j*4] = *(const float4*)(Kp + j*4);
        *(float4*)&Vs[t][j*4] = *(const float4*)(Vp + j*4);
    }
    __syncthreads();

    float mx = -3.0e38f, lsum = 0.f;
    float4 a0 = {0,0,0,0}, a1 = {0,0,0,0}, a2 = {0,0,0,0}, a3 = {0,0,0,0};

    #pragma unroll 2
    for (int j = 0; j < SS; j += 2) {
        const float4* kr0 = (const float4*)Ks[j];
        const float4* kr1 = (const float4*)Ks[j+1];
        float4 ka0=kr0[0], ka1=kr0[1], ka2=kr0[2], ka3=kr0[3];
        float4 kb0=kr1[0], kb1=kr1[1], kb2=kr1[2], kb3=kr1[3];
        float sa = ((q0.x*ka0.x + q0.y*ka0.y) + (q0.z*ka0.z + q0.w*ka0.w))
                 + ((q1.x*ka1.x + q1.y*ka1.y) + (q1.z*ka1.z + q1.w*ka1.w))
                 + ((q2.x*ka2.x + q2.y*ka2.y) + (q2.z*ka2.z + q2.w*ka2.w))
                 + ((q3.x*ka3.x + q3.y*ka3.y) + (q3.z*ka3.z + q3.w*ka3.w));
        float sb = ((q0.x*kb0.x + q0.y*kb0.y) + (q0.z*kb0.z + q0.w*kb0.w))
                 + ((q1.x*kb1.x + q1.y*kb1.y) + (q1.z*kb1.z + q1.w*kb1.w))
                 + ((q2.x*kb2.x + q2.y*kb2.y) + (q2.z*kb2.z + q2.w*kb2.w))
                 + ((q3.x*kb3.x + q3.y*kb3.y) + (q3.z*kb3.z + q3.w*kb3.w));
        float mn = fmaxf(sa, sb);
        if (mn > mx) {
            float f = __expf(mx - mn);
            lsum *= f;
            a0.x*=f; a0.y*=f; a0.z*=f; a0.w*=f;
            a1.x*=f; a1.y*=f; a1.z*=f; a1.w*=f;
            a2.x*=f; a2.y*=f; a2.z*=f; a2.w*=f;
            a3.x*=f; a3.y*=f; a3.z*=f; a3.w*=f;
            mx = mn;
        }
        float pa = __expf(sa - mx);
        float pb = __expf(sb - mx);
        lsum += pa + pb;
        const float4* vr0 = (const float4*)Vs[j];
        const float4* vr1 = (const float4*)Vs[j+1];
        float4 va, vb;
        va = vr0[0]; vb = vr1[0];
        a0.x = fmaf(pa, va.x, fmaf(pb, vb.x, a0.x));
        a0.y = fmaf(pa, va.y, fmaf(pb, vb.y, a0.y));
        a0.z = fmaf(pa, va.z, fmaf(pb, vb.z, a0.z));
        a0.w = fmaf(pa, va.w, fmaf(pb, vb.w, a0.w));
        va = vr0[1]; vb = vr1[1];
        a1.x = fmaf(pa, va.x, fmaf(pb, vb.x, a1.x));
        a1.y = fmaf(pa, va.y, fmaf(pb, vb.y, a1.y));
        a1.z = fmaf(pa, va.z, fmaf(pb, vb.z, a1.z));
        a1.w = fmaf(pa, va.w, fmaf(pb, vb.w, a1.w));
        va = vr0[2]; vb = vr1[2];
        a2.x = fmaf(pa, va.x, fmaf(pb, vb.x, a2.x));
        a2.y = fmaf(pa, va.y, fmaf(pb, vb.y, a2.y));
        a2.z = fmaf(pa, va.z, fmaf(pb, vb.z, a2.z));
        a2.w = fmaf(pa, va.w, fmaf(pb, vb.w, a2.w));
        va = vr0[3]; vb = vr1[3];
        a3.x = fmaf(pa, va.x, fmaf(pb, vb.x, a3.x));
        a3.y = fmaf(pa, va.y, fmaf(pb, vb.y, a3.y));
        a3.z = fmaf(pa, va.z, fmaf(pb, vb.z, a3.z));
        a3.w = fmaf(pa, va.w, fmaf(pb, vb.w, a3.w));
    }

    float inv = 1.f / lsum;
    float* Op = g_Qb + base + (size_t)t*HH;   // overwrite own Q slice (no cross-thread reads)
    *(float4*)(Op +  0) = make_float4(a0.x*inv, a0.y*inv, a0.z*inv, a0.w*inv);
    *(float4*)(Op +  4) = make_float4(a1.x*inv, a1.y*inv, a1.z*inv, a1.w*inv);
    *(float4*)(Op +  8) = make_float4(a2.x*inv, a2.y*inv, a2.z*inv, a2.w*inv);
    *(float4*)(Op + 12) = make_float4(a3.x*inv, a3.y*inv, a3.z*inv, a3.w*inv);
}

// -------- fused O-projection + output head: out[m][v] = attn_o . weff[v] + beff[v] --------
__global__ void head_kernel(float* __restrict__ out) {
    const int gw   = (blockIdx.x * 256 + threadIdx.x) >> 5;
    const int lane = threadIdx.x & 31;
    if (gw >= VV*MM) return;
    const int v = gw >> 10;
    const int m = gw & 1023;
    float4 xv = *(const float4*)(g_Qb + (size_t)gw*HH + lane*4);
    float4 wv = *(const float4*)(g_weff + v*HH + lane*4);
    float s = xv.x*wv.x + xv.y*wv.y + xv.z*wv.z + xv.w*wv.w;
    #pragma unroll
    for (int o = 16; o > 0; o >>= 1) s += __shfl_xor_sync(0xffffffffu, s, o);
    if (lane == 0) out[(size_t)m*VV + v] = s + g_beff[v];
}

extern "C" void kernel_launch(void* const* d_in, const int* in_sizes, int n_in,
                              void* d_out, int out_size) {
    const float* x        = (const float*)d_in[0];
    const float* adjl     = (const float*)d_in[1];
    const float* var_emb  = (const float*)d_in[2];
    const float* temp_emb = (const float*)d_in[3];
    const float* mech_W   = (const float*)d_in[4];
    const float* mech_b   = (const float*)d_in[5];
    const float* ln_g     = (const float*)d_in[6];
    const float* ln_b     = (const float*)d_in[7];
    const float* Wq       = (const float*)d_in[8];
    const float* Wk       = (const float*)d_in[9];
    const float* Wv       = (const float*)d_in[10];
    const float* Wo       = (const float*)d_in[11];
    const float* bq       = (const float*)d_in[12];
    const float* bk       = (const float*)d_in[13];
    const float* bv       = (const float*)d_in[14];
    const float* bo       = (const float*)d_in[15];
    const float* out_W    = (const float*)d_in[16];
    const float* out_b    = (const float*)d_in[17];
    float* out = (float*)d_out;

    sigmoid_adj_kernel<<<(VV*VV*LLP1 + 255)/256, 256>>>(adjl);
    build_Wc_kernel<<<(KAB*HH + 255)/256, 256>>>(var_emb, temp_emb);
    build_weff_kernel<<<VV, 128>>>(Wo, bo, out_W, out_b);
    build_AB_kernel<<<dim3(VV, BB, 2), 128>>>(x);

    // causal z = AB @ Wc  -> Z1
    gemm2<2,KAB,true,true><<<dim3(16, VV), 256>>>(5, 0, nullptr, nullptr, nullptr, nullptr, 0);

    // mech layers: Z1 -> Z2 -> Z1 -> Z2
    gemm2<0,128,false,false><<<dim3(16, VV), 256>>>(0, 1, mech_W, mech_b, ln_g, ln_b, 0);
    gemm2<0,128,false,false><<<dim3(16, VV), 256>>>(1, 0, mech_W, mech_b, ln_g, ln_b, 1);
    gemm2<0,128,false,false><<<dim3(16, VV), 256>>>(0, 1, mech_W, mech_b, ln_g, ln_b, 2);

    // Q/K/V projections from Z2
    gemm2<1,128,false,false><<<dim3(16, VV), 256>>>(1, 2, Wq, bq, nullptr, nullptr, 0);
    gemm2<1,128,false,false><<<dim3(16, VV), 256>>>(1, 3, Wk, bk, nullptr, nullptr, 0);
    gemm2<1,128,false,false><<<dim3(16, VV), 256>>>(1, 4, Wv, bv, nullptr, nullptr, 0);

    // attention (writes output in-place over Q buffer)
    attn_kernel<<<dim3(NHH, VV, BB), 256>>>();

    // fused O-projection + output head
    head_kernel<<<VV*MM/8, 256>>>(out);
}